// round 13
// baseline (speedup 1.0000x reference)
#include <cuda_runtime.h>
#include <cuda_bf16.h>
#include <cstdint>

typedef __nv_bfloat16 bf16;

#define DM     256
#define TT     8
#define NH     4
#define DHD    64
#define NQKV   768
#define NBATCH 32768
#define MROWS  262144   // NBATCH * TT

// ---------------- scratch (device globals: allocation-free rule) ----------------
// Weights stored TRANSPOSED: [n][k] (k contiguous) so GEMM B staging is plain copies.
__device__ bf16  g_Wqkv_hi[NQKV * DM];
__device__ bf16  g_Wqkv_lo[NQKV * DM];
__device__ float g_bqkv[NQKV];
__device__ bf16  g_Wfc_hi[DM * DM];
__device__ bf16  g_Wfc_lo[DM * DM];
__device__ float g_QKV[(size_t)MROWS * NQKV];
__device__ bf16  g_Ohi[(size_t)MROWS * DM];
__device__ bf16  g_Olo[(size_t)MROWS * DM];

// ---------------- weight prep: transposed [n][k] hi/lo split ----------------
__global__ void prep_w_kernel(const float* __restrict__ Wq, const float* __restrict__ bq,
                              const float* __restrict__ Wk, const float* __restrict__ bk,
                              const float* __restrict__ Wv, const float* __restrict__ bv,
                              const float* __restrict__ Wfc)
{
    int i = blockIdx.x * blockDim.x + threadIdx.x;
    int stride = gridDim.x * blockDim.x;
    for (int idx = i; idx < NQKV * DM; idx += stride) {
        int j = idx >> 8, d = idx & 255;
        int sec = j >> 8;            // 0=q,1=k,2=v
        int h = (j & 255) >> 6;
        int e = j & 63;
        const float* W = (sec == 0) ? Wq : ((sec == 1) ? Wk : Wv);
        float w = W[(h * DM + d) * DHD + e];
        bf16 hi = __float2bfloat16(w);
        g_Wqkv_hi[idx] = hi;
        g_Wqkv_lo[idx] = __float2bfloat16(w - __bfloat162float(hi));
    }
    for (int idx = i; idx < DM * DM; idx += stride) {
        int n = idx >> 8, k = idx & 255;
        float w = Wfc[k * DM + n];
        bf16 hi = __float2bfloat16(w);
        g_Wfc_hi[idx] = hi;
        g_Wfc_lo[idx] = __float2bfloat16(w - __bfloat162float(hi));
    }
    for (int idx = i; idx < NQKV; idx += stride) {
        int sec = idx >> 8;
        int h = (idx & 255) >> 6;
        int e = idx & 63;
        const float* bsrc = (sec == 0) ? bq : ((sec == 1) ? bk : bv);
        g_bqkv[idx] = bsrc[h * DHD + e];
    }
}

// ---------------- mma / ldmatrix / cp.async helpers ----------------
__device__ __forceinline__ void mma_bf16(float c[4], const unsigned a[4], unsigned b0, unsigned b1)
{
    asm volatile(
        "mma.sync.aligned.m16n8k16.row.col.f32.bf16.bf16.f32 "
        "{%0,%1,%2,%3}, {%4,%5,%6,%7}, {%8,%9}, {%0,%1,%2,%3};\n"
        : "+f"(c[0]), "+f"(c[1]), "+f"(c[2]), "+f"(c[3])
        : "r"(a[0]), "r"(a[1]), "r"(a[2]), "r"(a[3]), "r"(b0), "r"(b1));
}
__device__ __forceinline__ void ldsm4(unsigned r[4], unsigned addr)
{
    asm volatile("ldmatrix.sync.aligned.m8n8.x4.shared.b16 {%0,%1,%2,%3}, [%4];"
                 : "=r"(r[0]), "=r"(r[1]), "=r"(r[2]), "=r"(r[3]) : "r"(addr));
}
__device__ __forceinline__ uint32_t smem_u32(const void* p) {
    uint32_t a;
    asm("{ .reg .u64 t; cvta.to.shared.u64 t, %1; cvt.u32.u64 %0, t; }" : "=r"(a) : "l"(p));
    return a;
}
__device__ __forceinline__ void cp16(uint32_t saddr, const void* gaddr)
{
    asm volatile("cp.async.cg.shared.global [%0], [%1], 16;" :: "r"(saddr), "l"(gaddr));
}
#define CP_COMMIT() asm volatile("cp.async.commit_group;" ::: "memory")
#define CP_WAIT0()  asm volatile("cp.async.wait_group 0;" ::: "memory")

// ---------------- split-3 GEMM: C[M,NTOT] = A(hi+lo) @ B(hi+lo)^T + bias ----------------
// CTA tile 128x64, K-chunks of 32, 2-stage cp.async pipeline, 8 warps (4M x 2N),
// warp tile 32x32 (32 accum regs) -> <=85 regs -> 3 CTAs/SM = 24 warps.
// Row pitch 40 bf16 (80B): 8-row ldsm groups hit 8 distinct 16B segments -> conflict-free.
#define SR2     40
#define TN      64
#define AASIZE  (128 * SR2 * 2)        // A array bytes (128 rows x 40 bf16)
#define BASIZE  (TN  * SR2 * 2)        // B array bytes (64 rows x 40 bf16)
#define OFF_AL  (AASIZE)
#define OFF_BH  (2 * AASIZE)
#define OFF_BL  (2 * AASIZE + BASIZE)
#define STAGEB  (2 * AASIZE + 2 * BASIZE)   // 30720
#define SMEM_PL_BYTES (2 * STAGEB)          // 61440

template<int NTOT, bool FIRST>
__global__ void __launch_bounds__(256, 3)
gemm_pl_kernel(const float* __restrict__ Xf, const float* __restrict__ bias_in,
               float* __restrict__ C_out)
{
    extern __shared__ char smem[];
    const uint32_t sbase = smem_u32(smem);

    const float* __restrict__ bias = FIRST ? g_bqkv : bias_in;
    float* __restrict__ C = FIRST ? g_QKV : C_out;
    const bf16* __restrict__ Bh = FIRST ? g_Wqkv_hi : g_Wfc_hi;
    const bf16* __restrict__ Bl = FIRST ? g_Wqkv_lo : g_Wfc_lo;

    const int tid = threadIdx.x;
    const int warp = tid >> 5, lane = tid & 31;
    const int gid = lane >> 2, tig = lane & 3;
    const int wm = (warp & 3) * 32;
    const int wn = (warp >> 2) * 32;
    const size_t m0 = (size_t)blockIdx.y * 128;
    const int n0 = blockIdx.x * TN;

    float acc[2][4][4];
    #pragma unroll
    for (int a = 0; a < 2; a++)
        #pragma unroll
        for (int b = 0; b < 4; b++)
            #pragma unroll
            for (int c = 0; c < 4; c++) acc[a][b][c] = 0.f;

    // A bf16 arrays: 128 rows x 32 cols = 512 x 16B chunks -> 2/thread.
    // B bf16 arrays: 64 rows x 32 cols = 256 chunks -> 1/thread.
    // FIRST A (fp32): 128 x 32 = 1024 float4 -> 4/thread.
    float4 axr[4];   // FIRST A staging registers

    auto issue_stage = [&](int c, int buf) {
        const int kc = c * 32;
        const uint32_t sb = sbase + buf * STAGEB;
        if (FIRST) {
            #pragma unroll
            for (int j = 0; j < 4; j++) {
                int u = tid + 256 * j;
                int row = u >> 3;
                int kk = (u & 7) * 4;
                axr[j] = *(const float4*)&Xf[(m0 + row) * DM + kc + kk];
            }
        } else {
            #pragma unroll
            for (int j = 0; j < 2; j++) {
                int u = tid + 256 * j;
                int row = u >> 2;
                int kk = (u & 3) * 8;
                size_t g = (m0 + row) * DM + kc + kk;
                uint32_t so = (uint32_t)(row * SR2 + kk) * 2;
                cp16(sb + so, &g_Ohi[g]);
                cp16(sb + OFF_AL + so, &g_Olo[g]);
            }
        }
        {
            int row = tid >> 2;
            int kk = (tid & 3) * 8;
            size_t g = (size_t)(n0 + row) * DM + kc + kk;
            uint32_t so = (uint32_t)(row * SR2 + kk) * 2;
            cp16(sb + OFF_BH + so, &Bh[g]);
            cp16(sb + OFF_BL + so, &Bl[g]);
        }
        CP_COMMIT();
    };

    auto sts_convert = [&](int buf) {
        if (!FIRST) return;
        char* sb = smem + buf * STAGEB;
        #pragma unroll
        for (int j = 0; j < 4; j++) {
            int u = tid + 256 * j;
            int row = u >> 3;
            int kk = (u & 7) * 4;
            float4 v = axr[j];
            bf16 hx = __float2bfloat16(v.x), hy = __float2bfloat16(v.y);
            bf16 hz = __float2bfloat16(v.z), hw = __float2bfloat16(v.w);
            union { __nv_bfloat162 h2[2]; uint2 u2; } ph, pl;
            ph.h2[0] = __nv_bfloat162(hx, hy);
            ph.h2[1] = __nv_bfloat162(hz, hw);
            pl.h2[0] = __nv_bfloat162(__float2bfloat16(v.x - __bfloat162float(hx)),
                                      __float2bfloat16(v.y - __bfloat162float(hy)));
            pl.h2[1] = __nv_bfloat162(__float2bfloat16(v.z - __bfloat162float(hz)),
                                      __float2bfloat16(v.w - __bfloat162float(hw)));
            uint32_t so = (uint32_t)(row * SR2 + kk) * 2;
            *(uint2*)(sb + so) = ph.u2;
            *(uint2*)(sb + OFF_AL + so) = pl.u2;
        }
    };

    // ---- prologue: stage chunk 0 into buffer 0 ----
    issue_stage(0, 0);
    sts_convert(0);
    CP_WAIT0();
    __syncthreads();

    // ---- main pipeline: 8 chunks of K=32 ----
    for (int c = 0; c < 8; c++) {
        const int cur = c & 1;
        const bool more = (c + 1 < 8);
        if (more) issue_stage(c + 1, cur ^ 1);

        const uint32_t uS  = sbase + cur * STAGEB;
        const uint32_t uAh = uS;
        const uint32_t uAl = uS + OFF_AL;
        const uint32_t uBh = uS + OFF_BH;
        const uint32_t uBl = uS + OFF_BL;
        #pragma unroll
        for (int ks = 0; ks < 2; ks++) {
            const int kb = ks * 16;
            const int arow = wm + (lane & 15);
            const int acol = kb + ((lane >> 4) << 3);
            unsigned ah[2][4], al[2][4];
            #pragma unroll
            for (int mt = 0; mt < 2; mt++) {
                unsigned off = (unsigned)(((arow + mt * 16) * SR2 + acol) * 2);
                ldsm4(ah[mt], uAh + off);
                ldsm4(al[mt], uAl + off);
            }
            const int brr = ((lane >> 4) << 3) + (lane & 7);
            const int bcol = kb + (((lane >> 3) & 1) << 3);
            #pragma unroll
            for (int np = 0; np < 2; np++) {
                unsigned off = (unsigned)(((wn + np * 16 + brr) * SR2 + bcol) * 2);
                unsigned bh[4], bl[4];
                ldsm4(bh, uBh + off);
                ldsm4(bl, uBl + off);
                #pragma unroll
                for (int mt = 0; mt < 2; mt++) {
                    mma_bf16(acc[mt][2 * np],     ah[mt], bh[0], bh[1]);
                    mma_bf16(acc[mt][2 * np],     ah[mt], bl[0], bl[1]);
                    mma_bf16(acc[mt][2 * np],     al[mt], bh[0], bh[1]);
                    mma_bf16(acc[mt][2 * np + 1], ah[mt], bh[2], bh[3]);
                    mma_bf16(acc[mt][2 * np + 1], ah[mt], bl[2], bl[3]);
                    mma_bf16(acc[mt][2 * np + 1], al[mt], bh[2], bh[3]);
                }
            }
        }
        __syncthreads();               // all warps done with buf cur
        if (more) {
            sts_convert(cur ^ 1);      // FIRST: write converted A into next buffer
            CP_WAIT0();                // next stage cp.async arrived
            __syncthreads();           // next buffer visible to all warps
        }
    }

    // ---- epilogue: + bias, fp32 store ----
    #pragma unroll
    for (int mt = 0; mt < 2; mt++) {
        #pragma unroll
        for (int nt = 0; nt < 4; nt++) {
            int cn = n0 + wn + nt * 8 + tig * 2;
            float b0 = bias[cn], b1 = bias[cn + 1];
            size_t r = m0 + wm + mt * 16 + gid;
            float2 v0 = make_float2(acc[mt][nt][0] + b0, acc[mt][nt][1] + b1);
            float2 v1 = make_float2(acc[mt][nt][2] + b0, acc[mt][nt][3] + b1);
            *(float2*)&C[r * NTOT + cn] = v0;
            *(float2*)&C[(r + 8) * NTOT + cn] = v1;
        }
    }
}

// ---------------- causal attention: one warp per (batch, head), register q, LDS.128 k/v ----------------
__global__ void __launch_bounds__(256) attn_kernel()
{
    __shared__ float skv[8][2][TT][80];

    const int warp = threadIdx.x >> 5, lane = threadIdx.x & 31;
    const int task = blockIdx.x * 8 + warp;
    const int b = task >> 2, h = task & 3;

    const float* base = g_QKV + (size_t)b * TT * NQKV + h * DHD;
    const int t = lane >> 2;
    const int sb = lane & 3;

    #pragma unroll
    for (int j = 0; j < 4; j++) {
        int idx = j * 32 + lane;
        int s = idx >> 4;
        int u = idx & 15;
        int f = ((u & 3) << 2) | (u >> 2);
        float4 kk = *(const float4*)&base[s * NQKV + 256 + f * 4];
        float4 vv = *(const float4*)&base[s * NQKV + 512 + f * 4];
        ((float4*)&skv[warp][0][s][0])[u] = kk;
        ((float4*)&skv[warp][1][s][0])[u] = vv;
    }
    float4 q4[4];
    #pragma unroll
    for (int i = 0; i < 4; i++)
        q4[i] = *(const float4*)&base[t * NQKV + sb * 16 + i * 4];
    __syncwarp();

    float sc[TT];
    #pragma unroll
    for (int s = 0; s < TT; s++) {
        float p = 0.f;
        #pragma unroll
        for (int i = 0; i < 4; i++) {
            float4 kk = ((const float4*)&skv[warp][0][s][0])[i * 4 + sb];
            p += q4[i].x * kk.x + q4[i].y * kk.y + q4[i].z * kk.z + q4[i].w * kk.w;
        }
        sc[s] = p;
    }
    #pragma unroll
    for (int s = 0; s < TT; s++) {
        sc[s] += __shfl_xor_sync(0xffffffffu, sc[s], 1);
        sc[s] += __shfl_xor_sync(0xffffffffu, sc[s], 2);
        sc[s] = (s <= t) ? sc[s] * 0.125f : -1e30f;
    }
    float m = sc[0];
    #pragma unroll
    for (int s = 1; s < TT; s++) m = fmaxf(m, sc[s]);
    float wsum = 0.f;
    float wei[TT];
    #pragma unroll
    for (int s = 0; s < TT; s++) { wei[s] = __expf(sc[s] - m); wsum += wei[s]; }
    float inv = 1.0f / wsum;
    #pragma unroll
    for (int s = 0; s < TT; s++) wei[s] *= inv;

    const size_t orow = ((size_t)b * TT + t) * DM + h * DHD + sb * 16;
    #pragma unroll
    for (int i = 0; i < 4; i++) {
        float4 acc = make_float4(0.f, 0.f, 0.f, 0.f);
        #pragma unroll
        for (int s = 0; s < TT; s++) {
            float4 vv = ((const float4*)&skv[warp][1][s][0])[i * 4 + sb];
            acc.x += wei[s] * vv.x; acc.y += wei[s] * vv.y;
            acc.z += wei[s] * vv.z; acc.w += wei[s] * vv.w;
        }
        bf16 hx = __float2bfloat16(acc.x), hy = __float2bfloat16(acc.y);
        bf16 hz = __float2bfloat16(acc.z), hw = __float2bfloat16(acc.w);
        union { __nv_bfloat162 h2[2]; uint2 u2; } ph, pl;
        ph.h2[0] = __nv_bfloat162(hx, hy);
        ph.h2[1] = __nv_bfloat162(hz, hw);
        pl.h2[0] = __nv_bfloat162(__float2bfloat16(acc.x - __bfloat162float(hx)),
                                  __float2bfloat16(acc.y - __bfloat162float(hy)));
        pl.h2[1] = __nv_bfloat162(__float2bfloat16(acc.z - __bfloat162float(hz)),
                                  __float2bfloat16(acc.w - __bfloat162float(hw)));
        *(uint2*)&g_Ohi[orow + i * 4] = ph.u2;
        *(uint2*)&g_Olo[orow + i * 4] = pl.u2;
    }
}

// ---------------- launch ----------------
extern "C" void kernel_launch(void* const* d_in, const int* in_sizes, int n_in,
                              void* d_out, int out_size)
{
    const float* x   = (const float*)d_in[0];
    const float* Wq  = (const float*)d_in[1];
    const float* bq  = (const float*)d_in[2];
    const float* Wk  = (const float*)d_in[3];
    const float* bk  = (const float*)d_in[4];
    const float* Wv  = (const float*)d_in[5];
    const float* bv  = (const float*)d_in[6];
    const float* Wfc = (const float*)d_in[7];
    const float* bfc = (const float*)d_in[8];
    float* out = (float*)d_out;

    cudaFuncSetAttribute(gemm_pl_kernel<NQKV, true>,
                         cudaFuncAttributeMaxDynamicSharedMemorySize, SMEM_PL_BYTES);
    cudaFuncSetAttribute(gemm_pl_kernel<DM, false>,
                         cudaFuncAttributeMaxDynamicSharedMemorySize, SMEM_PL_BYTES);

    prep_w_kernel<<<192, 256>>>(Wq, bq, Wk, bk, Wv, bv, Wfc);

    // GEMM1: QKV = split(x) @ Wqkv + bqkv (x split fused into A-staging)
    gemm_pl_kernel<NQKV, true>
        <<<dim3(NQKV / TN, MROWS / 128), 256, SMEM_PL_BYTES>>>(x, nullptr, nullptr);

    // attention: 8 (batch,head) tasks per CTA (one per warp)
    attn_kernel<<<(NBATCH * NH) / 8, 256>>>();

    // GEMM2: out = split(O) @ Wfc + bfc
    gemm_pl_kernel<DM, false>
        <<<dim3(DM / TN, MROWS / 128), 256, SMEM_PL_BYTES>>>(nullptr, bfc, out);
}

// round 15
// speedup vs baseline: 1.2454x; 1.2454x over previous
#include <cuda_runtime.h>
#include <cuda_fp16.h>
#include <cstdint>

typedef __half fp16;

#define DM     256
#define TT     8
#define NH     4
#define DHD    64
#define NQKV   768
#define NBATCH 32768
#define MROWS  262144   // NBATCH * TT

// ---------------- scratch (device globals: allocation-free rule) ----------------
// Weights stored TRANSPOSED: [n][k] (k contiguous) so GEMM B staging is plain copies.
__device__ fp16  g_Wqkv_hi[NQKV * DM];
__device__ fp16  g_Wqkv_lo[NQKV * DM];
__device__ float g_bqkv[NQKV];
__device__ fp16  g_Wfc_hi[DM * DM];
__device__ fp16  g_Wfc_lo[DM * DM];
__device__ float g_QKV[(size_t)MROWS * NQKV];
__device__ fp16  g_Ohi[(size_t)MROWS * DM];
__device__ fp16  g_Olo[(size_t)MROWS * DM];

// ---------------- weight prep: transposed [n][k] hi/lo fp16 split ----------------
__global__ void prep_w_kernel(const float* __restrict__ Wq, const float* __restrict__ bq,
                              const float* __restrict__ Wk, const float* __restrict__ bk,
                              const float* __restrict__ Wv, const float* __restrict__ bv,
                              const float* __restrict__ Wfc)
{
    int i = blockIdx.x * blockDim.x + threadIdx.x;
    int stride = gridDim.x * blockDim.x;
    for (int idx = i; idx < NQKV * DM; idx += stride) {
        int j = idx >> 8, d = idx & 255;
        int sec = j >> 8;            // 0=q,1=k,2=v
        int h = (j & 255) >> 6;
        int e = j & 63;
        const float* W = (sec == 0) ? Wq : ((sec == 1) ? Wk : Wv);
        float w = W[(h * DM + d) * DHD + e];
        fp16 hi = __float2half_rn(w);
        g_Wqkv_hi[idx] = hi;
        g_Wqkv_lo[idx] = __float2half_rn(w - __half2float(hi));
    }
    for (int idx = i; idx < DM * DM; idx += stride) {
        int n = idx >> 8, k = idx & 255;
        float w = Wfc[k * DM + n];
        fp16 hi = __float2half_rn(w);
        g_Wfc_hi[idx] = hi;
        g_Wfc_lo[idx] = __float2half_rn(w - __half2float(hi));
    }
    for (int idx = i; idx < NQKV; idx += stride) {
        int sec = idx >> 8;
        int h = (idx & 255) >> 6;
        int e = idx & 63;
        const float* bsrc = (sec == 0) ? bq : ((sec == 1) ? bk : bv);
        g_bqkv[idx] = bsrc[h * DHD + e];
    }
}

// ---------------- mma / ldmatrix / cp.async helpers ----------------
__device__ __forceinline__ void mma_f16(float c[4], const unsigned a[4], unsigned b0, unsigned b1)
{
    asm volatile(
        "mma.sync.aligned.m16n8k16.row.col.f32.f16.f16.f32 "
        "{%0,%1,%2,%3}, {%4,%5,%6,%7}, {%8,%9}, {%0,%1,%2,%3};\n"
        : "+f"(c[0]), "+f"(c[1]), "+f"(c[2]), "+f"(c[3])
        : "r"(a[0]), "r"(a[1]), "r"(a[2]), "r"(a[3]), "r"(b0), "r"(b1));
}
__device__ __forceinline__ void ldsm4(unsigned r[4], unsigned addr)
{
    asm volatile("ldmatrix.sync.aligned.m8n8.x4.shared.b16 {%0,%1,%2,%3}, [%4];"
                 : "=r"(r[0]), "=r"(r[1]), "=r"(r[2]), "=r"(r[3]) : "r"(addr));
}
__device__ __forceinline__ uint32_t smem_u32(const void* p) {
    uint32_t a;
    asm("{ .reg .u64 t; cvta.to.shared.u64 t, %1; cvt.u32.u64 %0, t; }" : "=r"(a) : "l"(p));
    return a;
}
__device__ __forceinline__ void cp16(uint32_t saddr, const void* gaddr)
{
    asm volatile("cp.async.cg.shared.global [%0], [%1], 16;" :: "r"(saddr), "l"(gaddr));
}
#define CP_COMMIT() asm volatile("cp.async.commit_group;" ::: "memory")
#define CP_WAIT0()  asm volatile("cp.async.wait_group 0;" ::: "memory")

// ---------------- split GEMM: C[M,NTOT] = A @ B^T + bias ----------------
// CTA tile 128x128, K-chunks of 32, 2-stage cp.async pipeline, 8 warps (4M x 2N),
// warp tile 32x64.
// GEMM1 (FIRST): A = fp16(x) single array, B = W hi+lo -> 2 MMAs/product.
// GEMM2 (!FIRST): A = O hi+lo, B = Wfc hi+lo -> 3 MMAs/product.
// Row pitch 40 fp16 (80B): 8-row ldsm groups hit 8 distinct 16B segments -> conflict-free.
#define SR2     40
#define ASZ     (128 * SR2 * 2)        // bytes per array (128 rows x 40 fp16) = 10240

template<int NTOT, bool FIRST>
__global__ void __launch_bounds__(256, 2)
gemm_pl_kernel(const float* __restrict__ Xf, const float* __restrict__ bias_in,
               float* __restrict__ C_out)
{
    // stage layout: FIRST: [A][BH][BL]   else: [AH][AL][BH][BL]
    constexpr int OFF_AL  = ASZ;                       // !FIRST only
    constexpr int OFF_BH  = FIRST ? ASZ     : 2 * ASZ;
    constexpr int OFF_BL  = FIRST ? 2 * ASZ : 3 * ASZ;
    constexpr int STAGEB  = FIRST ? 3 * ASZ : 4 * ASZ;

    extern __shared__ char smem[];
    const uint32_t sbase = smem_u32(smem);

    const float* __restrict__ bias = FIRST ? g_bqkv : bias_in;
    float* __restrict__ C = FIRST ? g_QKV : C_out;
    const fp16* __restrict__ Bh = FIRST ? g_Wqkv_hi : g_Wfc_hi;
    const fp16* __restrict__ Bl = FIRST ? g_Wqkv_lo : g_Wfc_lo;

    const int tid = threadIdx.x;
    const int warp = tid >> 5, lane = tid & 31;
    const int gid = lane >> 2, tig = lane & 3;
    const int wm = (warp & 3) * 32;
    const int wn = (warp >> 2) * 64;
    const size_t m0 = (size_t)blockIdx.y * 128;
    const int n0 = blockIdx.x * 128;

    float acc[2][8][4];
    #pragma unroll
    for (int a = 0; a < 2; a++)
        #pragma unroll
        for (int b = 0; b < 8; b++)
            #pragma unroll
            for (int c = 0; c < 4; c++) acc[a][b][c] = 0.f;

    // fp16 arrays: 128 rows x 32 cols = 64B/row = 4 x 16B chunks/row, 512 chunks
    //   -> u = tid + 256*j (j<2), row = u>>2, kk = (u&3)*8.
    // FIRST A (fp32 x): 128 x 32 = 1024 float4 -> 4/thread: row = u>>3, kk = (u&7)*4.
    float4 axr[4];   // FIRST A staging registers

    auto issue_stage = [&](int c, int buf) {
        const int kc = c * 32;
        const uint32_t sb = sbase + buf * STAGEB;
        if (FIRST) {
            #pragma unroll
            for (int j = 0; j < 4; j++) {
                int u = tid + 256 * j;
                int row = u >> 3;
                int kk = (u & 7) * 4;
                axr[j] = *(const float4*)&Xf[(m0 + row) * DM + kc + kk];
            }
        } else {
            #pragma unroll
            for (int j = 0; j < 2; j++) {
                int u = tid + 256 * j;
                int row = u >> 2;
                int kk = (u & 3) * 8;
                size_t g = (m0 + row) * DM + kc + kk;
                uint32_t so = (uint32_t)(row * SR2 + kk) * 2;
                cp16(sb + so, &g_Ohi[g]);
                cp16(sb + OFF_AL + so, &g_Olo[g]);
            }
        }
        #pragma unroll
        for (int j = 0; j < 2; j++) {
            int u = tid + 256 * j;
            int row = u >> 2;
            int kk = (u & 3) * 8;
            size_t g = (size_t)(n0 + row) * DM + kc + kk;
            uint32_t so = (uint32_t)(row * SR2 + kk) * 2;
            cp16(sb + OFF_BH + so, &Bh[g]);
            cp16(sb + OFF_BL + so, &Bl[g]);
        }
        CP_COMMIT();
    };

    auto sts_convert = [&](int buf) {
        if (!FIRST) return;
        char* sb = smem + buf * STAGEB;
        #pragma unroll
        for (int j = 0; j < 4; j++) {
            int u = tid + 256 * j;
            int row = u >> 3;
            int kk = (u & 7) * 4;
            float4 v = axr[j];
            union { __half2 h2[2]; uint2 u2; } p;
            p.h2[0] = __halves2half2(__float2half_rn(v.x), __float2half_rn(v.y));
            p.h2[1] = __halves2half2(__float2half_rn(v.z), __float2half_rn(v.w));
            *(uint2*)(sb + (uint32_t)(row * SR2 + kk) * 2) = p.u2;
        }
    };

    // ---- prologue: stage chunk 0 into buffer 0 ----
    issue_stage(0, 0);
    sts_convert(0);
    CP_WAIT0();
    __syncthreads();

    // ---- main pipeline: 8 chunks of K=32 ----
    for (int c = 0; c < 8; c++) {
        const int cur = c & 1;
        const bool more = (c + 1 < 8);
        if (more) issue_stage(c + 1, cur ^ 1);

        const uint32_t uS  = sbase + cur * STAGEB;
        const uint32_t uAh = uS;
        const uint32_t uAl = uS + OFF_AL;
        const uint32_t uBh = uS + OFF_BH;
        const uint32_t uBl = uS + OFF_BL;
        #pragma unroll
        for (int ks = 0; ks < 2; ks++) {
            const int kb = ks * 16;
            const int arow = wm + (lane & 15);
            const int acol = kb + ((lane >> 4) << 3);
            unsigned ah[2][4], al[2][4];
            #pragma unroll
            for (int mt = 0; mt < 2; mt++) {
                unsigned off = (unsigned)(((arow + mt * 16) * SR2 + acol) * 2);
                ldsm4(ah[mt], uAh + off);
                if (!FIRST) ldsm4(al[mt], uAl + off);
            }
            const int brr = ((lane >> 4) << 3) + (lane & 7);
            const int bcol = kb + (((lane >> 3) & 1) << 3);
            #pragma unroll
            for (int nph = 0; nph < 2; nph++) {
                unsigned bh[2][4], bl[2][4];
                #pragma unroll
                for (int p = 0; p < 2; p++) {
                    int np = 2 * nph + p;
                    unsigned off = (unsigned)(((wn + np * 16 + brr) * SR2 + bcol) * 2);
                    ldsm4(bh[p], uBh + off);
                    ldsm4(bl[p], uBl + off);
                }
                // term-major issue: each acc's MMAs separated by 8 independents
                #pragma unroll
                for (int p = 0; p < 2; p++) {
                    int nt = 2 * (2 * nph + p);
                    #pragma unroll
                    for (int mt = 0; mt < 2; mt++) {
                        mma_f16(acc[mt][nt],     ah[mt], bh[p][0], bh[p][1]);
                        mma_f16(acc[mt][nt + 1], ah[mt], bh[p][2], bh[p][3]);
                    }
                }
                #pragma unroll
                for (int p = 0; p < 2; p++) {
                    int nt = 2 * (2 * nph + p);
                    #pragma unroll
                    for (int mt = 0; mt < 2; mt++) {
                        mma_f16(acc[mt][nt],     ah[mt], bl[p][0], bl[p][1]);
                        mma_f16(acc[mt][nt + 1], ah[mt], bl[p][2], bl[p][3]);
                    }
                }
                if (!FIRST) {
                    #pragma unroll
                    for (int p = 0; p < 2; p++) {
                        int nt = 2 * (2 * nph + p);
                        #pragma unroll
                        for (int mt = 0; mt < 2; mt++) {
                            mma_f16(acc[mt][nt],     al[mt], bh[p][0], bh[p][1]);
                            mma_f16(acc[mt][nt + 1], al[mt], bh[p][2], bh[p][3]);
                        }
                    }
                }
            }
        }
        __syncthreads();               // all warps done with buf cur
        if (more) {
            sts_convert(cur ^ 1);      // FIRST: write converted A into next buffer
            CP_WAIT0();                // next stage cp.async arrived
            __syncthreads();           // next buffer visible to all warps
        }
    }

    // ---- epilogue: + bias, fp32 store ----
    #pragma unroll
    for (int mt = 0; mt < 2; mt++) {
        #pragma unroll
        for (int nt = 0; nt < 8; nt++) {
            int cn = n0 + wn + nt * 8 + tig * 2;
            float b0 = bias[cn], b1 = bias[cn + 1];
            size_t r = m0 + wm + mt * 16 + gid;
            float2 v0 = make_float2(acc[mt][nt][0] + b0, acc[mt][nt][1] + b1);
            float2 v1 = make_float2(acc[mt][nt][2] + b0, acc[mt][nt][3] + b1);
            *(float2*)&C[r * NTOT + cn] = v0;
            *(float2*)&C[(r + 8) * NTOT + cn] = v1;
        }
    }
}

// ---------------- causal attention: one warp per (batch, head), register q, LDS.128 k/v ----------------
__global__ void __launch_bounds__(256) attn_kernel()
{
    __shared__ float skv[8][2][TT][80];

    const int warp = threadIdx.x >> 5, lane = threadIdx.x & 31;
    const int task = blockIdx.x * 8 + warp;
    const int b = task >> 2, h = task & 3;

    const float* base = g_QKV + (size_t)b * TT * NQKV + h * DHD;
    const int t = lane >> 2;
    const int sb = lane & 3;

    #pragma unroll
    for (int j = 0; j < 4; j++) {
        int idx = j * 32 + lane;
        int s = idx >> 4;
        int u = idx & 15;
        int f = ((u & 3) << 2) | (u >> 2);
        float4 kk = *(const float4*)&base[s * NQKV + 256 + f * 4];
        float4 vv = *(const float4*)&base[s * NQKV + 512 + f * 4];
        ((float4*)&skv[warp][0][s][0])[u] = kk;
        ((float4*)&skv[warp][1][s][0])[u] = vv;
    }
    float4 q4[4];
    #pragma unroll
    for (int i = 0; i < 4; i++)
        q4[i] = *(const float4*)&base[t * NQKV + sb * 16 + i * 4];
    __syncwarp();

    float sc[TT];
    #pragma unroll
    for (int s = 0; s < TT; s++) {
        float p = 0.f;
        #pragma unroll
        for (int i = 0; i < 4; i++) {
            float4 kk = ((const float4*)&skv[warp][0][s][0])[i * 4 + sb];
            p += q4[i].x * kk.x + q4[i].y * kk.y + q4[i].z * kk.z + q4[i].w * kk.w;
        }
        sc[s] = p;
    }
    #pragma unroll
    for (int s = 0; s < TT; s++) {
        sc[s] += __shfl_xor_sync(0xffffffffu, sc[s], 1);
        sc[s] += __shfl_xor_sync(0xffffffffu, sc[s], 2);
        sc[s] = (s <= t) ? sc[s] * 0.125f : -1e30f;
    }
    float m = sc[0];
    #pragma unroll
    for (int s = 1; s < TT; s++) m = fmaxf(m, sc[s]);
    float wsum = 0.f;
    float wei[TT];
    #pragma unroll
    for (int s = 0; s < TT; s++) { wei[s] = __expf(sc[s] - m); wsum += wei[s]; }
    float inv = 1.0f / wsum;
    #pragma unroll
    for (int s = 0; s < TT; s++) wei[s] *= inv;

    const size_t orow = ((size_t)b * TT + t) * DM + h * DHD + sb * 16;
    #pragma unroll
    for (int i = 0; i < 4; i++) {
        float4 acc = make_float4(0.f, 0.f, 0.f, 0.f);
        #pragma unroll
        for (int s = 0; s < TT; s++) {
            float4 vv = ((const float4*)&skv[warp][1][s][0])[i * 4 + sb];
            acc.x += wei[s] * vv.x; acc.y += wei[s] * vv.y;
            acc.z += wei[s] * vv.z; acc.w += wei[s] * vv.w;
        }
        fp16 hx = __float2half_rn(acc.x), hy = __float2half_rn(acc.y);
        fp16 hz = __float2half_rn(acc.z), hw = __float2half_rn(acc.w);
        union { __half2 h2[2]; uint2 u2; } ph, pl;
        ph.h2[0] = __halves2half2(hx, hy);
        ph.h2[1] = __halves2half2(hz, hw);
        pl.h2[0] = __halves2half2(__float2half_rn(acc.x - __half2float(hx)),
                                  __float2half_rn(acc.y - __half2float(hy)));
        pl.h2[1] = __halves2half2(__float2half_rn(acc.z - __half2float(hz)),
                                  __float2half_rn(acc.w - __half2float(hw)));
        *(uint2*)&g_Ohi[orow + i * 4] = ph.u2;
        *(uint2*)&g_Olo[orow + i * 4] = pl.u2;
    }
}

// ---------------- launch ----------------
extern "C" void kernel_launch(void* const* d_in, const int* in_sizes, int n_in,
                              void* d_out, int out_size)
{
    const float* x   = (const float*)d_in[0];
    const float* Wq  = (const float*)d_in[1];
    const float* bq  = (const float*)d_in[2];
    const float* Wk  = (const float*)d_in[3];
    const float* bk  = (const float*)d_in[4];
    const float* Wv  = (const float*)d_in[5];
    const float* bv  = (const float*)d_in[6];
    const float* Wfc = (const float*)d_in[7];
    const float* bfc = (const float*)d_in[8];
    float* out = (float*)d_out;

    cudaFuncSetAttribute(gemm_pl_kernel<NQKV, true>,
                         cudaFuncAttributeMaxDynamicSharedMemorySize, 2 * 3 * ASZ);
    cudaFuncSetAttribute(gemm_pl_kernel<DM, false>,
                         cudaFuncAttributeMaxDynamicSharedMemorySize, 2 * 4 * ASZ);

    prep_w_kernel<<<192, 256>>>(Wq, bq, Wk, bk, Wv, bv, Wfc);

    // GEMM1 (2-term fp16): QKV = fp16(x) @ (Wqkv hi+lo) + bqkv
    gemm_pl_kernel<NQKV, true>
        <<<dim3(NQKV / 128, MROWS / 128), 256, 2 * 3 * ASZ>>>(x, nullptr, nullptr);

    // attention: 8 (batch,head) tasks per CTA (one per warp)
    attn_kernel<<<(NBATCH * NH) / 8, 256>>>();

    // GEMM2 (3-term fp16): out = (O hi+lo) @ (Wfc hi+lo) + bfc
    gemm_pl_kernel<DM, false>
        <<<dim3(DM / 128, MROWS / 128), 256, 2 * 4 * ASZ>>>(nullptr, bfc, out);
}